// round 10
// baseline (speedup 1.0000x reference)
#include <cuda_runtime.h>
#include <cuda_bf16.h>

#define DM 2048
#define NB 32
#define NT 8
#define NH 32
#define DH 64
#define CT 1016
#define SEQ 1024
#define MROWS 256   // NB*NT

// ---------------- scratch (device globals; no allocation allowed) ----------------
__device__ float g_q   [NB*NH*NT*DH];   // [b][h][t][d]
__device__ float g_kn  [NB*NH*NT*DH];
__device__ float g_vn  [NB*NH*NT*DH];
__device__ float g_part0[MROWS*DM];     // oproj K-split partials
__device__ float g_part1[MROWS*DM];

// bf16 hi/lo split scratch
__device__ __align__(16) __nv_bfloat16 g_wqh[DM*DM], g_wql[DM*DM];
__device__ __align__(16) __nv_bfloat16 g_wkh[DM*DM], g_wkl[DM*DM];
__device__ __align__(16) __nv_bfloat16 g_wvh[DM*DM], g_wvl[DM*DM];
__device__ __align__(16) __nv_bfloat16 g_woh[DM*DM], g_wol[DM*DM];
__device__ __align__(16) __nv_bfloat16 g_xh[MROWS*DM], g_xl[MROWS*DM];
__device__ __align__(16) __nv_bfloat16 g_ah[MROWS*DM], g_al[MROWS*DM];  // attn out split

// ---------------- cp.async helpers ----------------
__device__ __forceinline__ void cp16(unsigned dst, const void* src) {
    asm volatile("cp.async.cg.shared.global [%0], [%1], 16;\n" :: "r"(dst), "l"(src));
}
__device__ __forceinline__ void cp_commit() {
    asm volatile("cp.async.commit_group;\n");
}
__device__ __forceinline__ void cp_wait1() {
    asm volatile("cp.async.wait_group 1;\n");
}
__device__ __forceinline__ void cp_wait0() {
    asm volatile("cp.async.wait_group 0;\n");
}

// ---------------- mma / ldmatrix helpers ----------------
__device__ __forceinline__ void ldm_x4(unsigned addr, unsigned& r0, unsigned& r1,
                                       unsigned& r2, unsigned& r3) {
    asm volatile("ldmatrix.sync.aligned.m8n8.x4.shared.b16 {%0,%1,%2,%3}, [%4];"
                 : "=r"(r0), "=r"(r1), "=r"(r2), "=r"(r3) : "r"(addr));
}
__device__ __forceinline__ void mma16(float* c, const unsigned* a, unsigned b0, unsigned b1) {
    asm volatile(
        "mma.sync.aligned.m16n8k16.row.col.f32.bf16.bf16.f32 "
        "{%0,%1,%2,%3}, {%4,%5,%6,%7}, {%8,%9}, {%0,%1,%2,%3};"
        : "+f"(c[0]), "+f"(c[1]), "+f"(c[2]), "+f"(c[3])
        : "r"(a[0]), "r"(a[1]), "r"(a[2]), "r"(a[3]), "r"(b0), "r"(b1));
}

// =================================================================================
// Prepass: split fp32 -> bf16 hi/lo for 4 weights + x
// =================================================================================
__device__ __forceinline__ void split8_store(const float4 f0, const float4 f1,
                                             __nv_bfloat16* dh, __nv_bfloat16* dl, size_t off) {
    float a[8] = {f0.x, f0.y, f0.z, f0.w, f1.x, f1.y, f1.z, f1.w};
    unsigned short h[8], l[8];
#pragma unroll
    for (int i = 0; i < 8; i++) {
        __nv_bfloat16 hb = __float2bfloat16(a[i]);
        __nv_bfloat16 lb = __float2bfloat16(a[i] - __bfloat162float(hb));
        h[i] = __bfloat16_as_ushort(hb);
        l[i] = __bfloat16_as_ushort(lb);
    }
    uint4 hs, ls;
    hs.x = (unsigned)h[0] | ((unsigned)h[1] << 16);
    hs.y = (unsigned)h[2] | ((unsigned)h[3] << 16);
    hs.z = (unsigned)h[4] | ((unsigned)h[5] << 16);
    hs.w = (unsigned)h[6] | ((unsigned)h[7] << 16);
    ls.x = (unsigned)l[0] | ((unsigned)l[1] << 16);
    ls.y = (unsigned)l[2] | ((unsigned)l[3] << 16);
    ls.z = (unsigned)l[4] | ((unsigned)l[5] << 16);
    ls.w = (unsigned)l[6] | ((unsigned)l[7] << 16);
    ((uint4*)dh)[off] = hs;
    ((uint4*)dl)[off] = ls;
}

#define W8 (DM * DM / 8)
#define X8 (MROWS * DM / 8)

__device__ __forceinline__ void conv_route(int id, const float* wq, const float* wk,
                                           const float* wv, const float* wo, const float* x,
                                           const float*& src, __nv_bfloat16*& dh,
                                           __nv_bfloat16*& dl, int& off) {
    if (id < W8)          { src = wq; dh = g_wqh; dl = g_wql; off = id; }
    else if (id < 2 * W8) { src = wk; dh = g_wkh; dl = g_wkl; off = id - W8; }
    else if (id < 3 * W8) { src = wv; dh = g_wvh; dl = g_wvl; off = id - 2 * W8; }
    else if (id < 4 * W8) { src = wo; dh = g_woh; dl = g_wol; off = id - 3 * W8; }
    else                  { src = x;  dh = g_xh;  dl = g_xl;  off = id - 4 * W8; }
}

__global__ __launch_bounds__(256) void conv_all(
    const float* __restrict__ wq, const float* __restrict__ wk,
    const float* __restrict__ wv, const float* __restrict__ wo,
    const float* __restrict__ x)
{
    const int total = 4 * W8 + X8;
    for (int id = blockIdx.x * 512 + threadIdx.x; id < total; id += gridDim.x * 512) {
        const int id2 = id + 256;
        const float *s0, *s1 = nullptr; __nv_bfloat16 *h0, *l0, *h1, *l1; int o0, o1;
        conv_route(id, wq, wk, wv, wo, x, s0, h0, l0, o0);
        float4 a0 = ((const float4*)s0)[(size_t)o0 * 2];
        float4 a1 = ((const float4*)s0)[(size_t)o0 * 2 + 1];
        float4 b0, b1;
        if (id2 < total) {
            conv_route(id2, wq, wk, wv, wo, x, s1, h1, l1, o1);
            b0 = ((const float4*)s1)[(size_t)o1 * 2];
            b1 = ((const float4*)s1)[(size_t)o1 * 2 + 1];
        }
        split8_store(a0, a1, h0, l0, o0);
        if (id2 < total) split8_store(b0, b1, h1, l1, o1);
    }
}

// =================================================================================
// bf16-split GEMM (3xBF16), BM=64 BN=64 BK=32, 256 thr.
// MODE 0: QKV full-K -> g_q/g_kn/g_vn (+bias).  MODE 1: O-proj K-split partials.
// =================================================================================
template<int MODE>
__global__ __launch_bounds__(256) void gemm_bf16(
    const float* __restrict__ bi0, const float* __restrict__ bi1,
    const float* __restrict__ bi2)
{
    __shared__ __align__(16) unsigned char smem[2 * 16384];

    const int tid  = threadIdx.x;
    const int lane = tid & 31;
    const int wid  = tid >> 5;
    const int gid  = lane >> 2;
    const int tig  = lane & 3;
    const int wm   = wid & 1;
    const int wn   = wid >> 1;
    const int bx = blockIdx.x;
    const int by = blockIdx.y;
    const int bz = blockIdx.z;

    const __nv_bfloat16 *Ah, *Al, *Bh, *Bl;
    const float* bsel = nullptr;
    float* dst = nullptr;
    float* pOut = nullptr;
    int nrow0;
    int it0, it1;
    if (MODE == 0) {
        const int type = by >> 5;
        Ah = g_xh; Al = g_xl;
        Bh = (type == 0) ? g_wqh : (type == 1) ? g_wkh : g_wvh;
        Bl = (type == 0) ? g_wql : (type == 1) ? g_wkl : g_wvl;
        bsel = (type == 0) ? bi0 : (type == 1) ? bi1 : bi2;
        dst  = (type == 0) ? g_q : (type == 1) ? g_kn : g_vn;
        nrow0 = (by & 31) * 64;
        it0 = 0; it1 = DM / 32;
    } else {
        Ah = g_ah; Al = g_al; Bh = g_woh; Bl = g_wol;
        pOut = bz ? g_part1 : g_part0;
        nrow0 = by * 64;
        it0 = bz * (DM / 64); it1 = it0 + DM / 64;
    }
    const int row0 = bx * 64;

    const unsigned sbase = (unsigned)__cvta_generic_to_shared(smem);

    const int sr = tid >> 2;
    const int sc = tid & 3;
    const unsigned sdst = sbase + (unsigned)(sr * 64 + (sc ^ ((sr >> 1) & 3)) * 16);
    const __nv_bfloat16* aSrc  = Ah + (size_t)(row0  + sr) * DM + sc * 8;
    const __nv_bfloat16* alSrc = Al + (size_t)(row0  + sr) * DM + sc * 8;
    const __nv_bfloat16* bSrc  = Bh + (size_t)(nrow0 + sr) * DM + sc * 8;
    const __nv_bfloat16* blSrc = Bl + (size_t)(nrow0 + sr) * DM + sc * 8;

    float acc[2][2][4];
#pragma unroll
    for (int i = 0; i < 2; i++)
#pragma unroll
        for (int j = 0; j < 2; j++)
#pragma unroll
            for (int q = 0; q < 4; q++) acc[i][j][q] = 0.f;

    const int a_l15 = lane & 15;
    const int ku_a  = lane >> 4;
    const int brow  = wn * 16 + ((lane & 7) | ((lane & 16) >> 1));
    const int ku_b  = (lane >> 3) & 1;

    {
        const int ko = it0 * 32;
        cp16(sdst,          aSrc  + ko);
        cp16(sdst + 4096u,  alSrc + ko);
        cp16(sdst + 8192u,  bSrc  + ko);
        cp16(sdst + 12288u, blSrc + ko);
        cp_commit();
    }

    for (int it = it0; it < it1; ++it) {
        if (it < it1 - 1) {
            const int ko = (it + 1) * 32;
            const unsigned d = sdst + (unsigned)(((it - it0 + 1) & 1) * 16384);
            cp16(d,          aSrc  + ko);
            cp16(d + 4096u,  alSrc + ko);
            cp16(d + 8192u,  bSrc  + ko);
            cp16(d + 12288u, blSrc + ko);
            cp_commit();
            cp_wait1();
        } else {
            cp_wait0();
        }
        __syncthreads();

        const unsigned sb = sbase + (unsigned)(((it - it0) & 1) * 16384);
#pragma unroll
        for (int ks = 0; ks < 2; ks++) {
            unsigned ah[2][4], al_[2][4], bh[4], bl[4];
#pragma unroll
            for (int i = 0; i < 2; i++) {
                const int r  = wm * 32 + i * 16 + a_l15;
                const int pu = (ks * 2 + ku_a) ^ ((r >> 1) & 3);
                const unsigned ad = sb + (unsigned)(r * 64 + pu * 16);
                ldm_x4(ad,         ah[i][0],  ah[i][1],  ah[i][2],  ah[i][3]);
                ldm_x4(ad + 4096u, al_[i][0], al_[i][1], al_[i][2], al_[i][3]);
            }
            {
                const int pu = (ks * 2 + ku_b) ^ ((brow >> 1) & 3);
                const unsigned bd = sb + 8192u + (unsigned)(brow * 64 + pu * 16);
                ldm_x4(bd,         bh[0], bh[1], bh[2], bh[3]);
                ldm_x4(bd + 4096u, bl[0], bl[1], bl[2], bl[3]);
            }
#pragma unroll
            for (int i = 0; i < 2; i++)
#pragma unroll
                for (int j = 0; j < 2; j++) {
                    mma16(acc[i][j], ah[i],  bh[2 * j], bh[2 * j + 1]);
                    mma16(acc[i][j], ah[i],  bl[2 * j], bl[2 * j + 1]);
                    mma16(acc[i][j], al_[i], bh[2 * j], bh[2 * j + 1]);
                }
        }
        __syncthreads();
    }

#pragma unroll
    for (int i = 0; i < 2; i++) {
#pragma unroll
        for (int j = 0; j < 2; j++) {
#pragma unroll
            for (int q = 0; q < 4; q++) {
                const int m = row0 + wm * 32 + i * 16 + gid + ((q >= 2) ? 8 : 0);
                const int n = nrow0 + wn * 16 + j * 8 + 2 * tig + (q & 1);
                if (MODE == 0) {
                    const float v = acc[i][j][q] + bsel[n];
                    const int h = n >> 6, d = n & 63;
                    const int bb = m >> 3, tt = m & 7;
                    dst[(((size_t)(bb * NH + h)) * NT + tt) * DH + d] = v;
                } else {
                    pOut[(size_t)m * DM + n] = acc[i][j][q];
                }
            }
        }
    }
}

// oproj partial reduce + bias -> out
__global__ __launch_bounds__(256) void reduce_bias(
    const float* __restrict__ bo, float* __restrict__ out)
{
    const int i = blockIdx.x * 256 + threadIdx.x;
    float4 a = ((const float4*)g_part0)[i];
    float4 b = ((const float4*)g_part1)[i];
    const int n4 = (i & (DM / 4 - 1)) * 4;
    float4 bb = *(const float4*)(bo + n4);
    float4 r;
    r.x = a.x + b.x + bb.x;
    r.y = a.y + b.y + bb.y;
    r.z = a.z + b.z + bb.z;
    r.w = a.w + b.w + bb.w;
    ((float4*)out)[i] = r;
}

// =================================================================================
// Flash attention, warp-per-row. Block = (b,h), 1024 blocks x 256 threads.
// smem: q[512] | p_buf[8*68=544] | kv[2 stages][K 64x68 + V 64x68] = 73856 B
// One pass over seq: per 64-tile, warp w computes row t=w's 64 scores (lane ->
// s=l, l+32), online softmax in registers/shfl, p via warp-private smem, then
// PV accumulation into a float2/lane (d=2l,2l+1). 2 syncthreads per tile.
// =================================================================================
#define KV_ROW 68
#define KV_TILE (64 * KV_ROW)     // 4352 floats
#define STAGE_F (2 * KV_TILE)     // K + V per stage
#define ATTN_SMEM_FLOATS (512 + 544 + 2 * STAGE_F)   // 18464 floats = 73856 B

__device__ __forceinline__ void stage_kv(unsigned base, int buf, int s0, int tid,
                                         const float* __restrict__ ck,
                                         const float* __restrict__ kn,
                                         const float* __restrict__ cv,
                                         const float* __restrict__ vn)
{
#pragma unroll
    for (int i = 0; i < 4; i++) {
        const int idx = tid + i * 256;
        const int sl  = idx >> 4;
        const int c4  = idx & 15;
        const int s   = s0 + sl;
        const float* ksrc = (s < CT) ? (ck + (size_t)s * DH + c4 * 4)
                                     : (kn + (size_t)(s - CT) * DH + c4 * 4);
        const float* vsrc = (s < CT) ? (cv + (size_t)s * DH + c4 * 4)
                                     : (vn + (size_t)(s - CT) * DH + c4 * 4);
        const unsigned off = (unsigned)((buf * STAGE_F + sl * KV_ROW + c4 * 4) * 4);
        cp16(base + off, ksrc);
        cp16(base + off + KV_TILE * 4, vsrc);
    }
    cp_commit();
}

__global__ __launch_bounds__(256) void attn_kernel(
    const float* __restrict__ cache_k,
    const float* __restrict__ cache_v)
{
    extern __shared__ float sm[];
    float* q_s   = sm;            // 512
    float* p_buf = sm + 512;      // 544 (8 rows x 68)
    float* kv    = p_buf + 544;   // 2 * STAGE_F

    const int tid = threadIdx.x;
    const int w   = tid >> 5;
    const int l   = tid & 31;
    const int bh  = blockIdx.x;
    const int b   = bh >> 5;
    const int h   = bh & 31;

    const float* qsrc = g_q + (size_t)bh * (NT * DH);
    q_s[tid]       = qsrc[tid]       * 0.125f;
    q_s[tid + 256] = qsrc[tid + 256] * 0.125f;

    const float* ck = cache_k + (size_t)bh * CT * DH;
    const float* cv = cache_v + (size_t)bh * CT * DH;
    const float* kn = g_kn + (size_t)bh * (NT * DH);
    const float* vn = g_vn + (size_t)bh * (NT * DH);

    const unsigned kv_addr = (unsigned)__cvta_generic_to_shared(kv);

    float m_run = -1e30f;
    float S = 0.f;
    float2 acc = make_float2(0.f, 0.f);

    stage_kv(kv_addr, 0, 0, tid, ck, kn, cv, vn);

    for (int c = 0; c < 16; c++) {
        if (c < 15) { stage_kv(kv_addr, (c + 1) & 1, (c + 1) * 64, tid, ck, kn, cv, vn); cp_wait1(); }
        else        { cp_wait0(); }
        __syncthreads();                      // tile c staged (and q_s on c==0)

        const float* kb = kv + (c & 1) * STAGE_F;
        const float* vb = kb + KV_TILE;

        // ---- scores: lane l -> s = l, l+32 of this tile, row t = w ----
        const float4* q4 = (const float4*)(q_s + w * DH);
        const float4* k0 = (const float4*)(kb + l * KV_ROW);
        const float4* k1 = (const float4*)(kb + (l + 32) * KV_ROW);
        float s0 = 0.f, s1 = 0.f;
#pragma unroll
        for (int i = 0; i < 16; i++) {
            float4 qq = q4[i];
            float4 a = k0[i];
            float4 bb = k1[i];
            s0 += a.x * qq.x + a.y * qq.y + a.z * qq.z + a.w * qq.w;
            s1 += bb.x * qq.x + bb.y * qq.y + bb.z * qq.z + bb.w * qq.w;
        }

        // ---- online softmax (warp-local) ----
        float mt = fmaxf(s0, s1);
#pragma unroll
        for (int o = 16; o; o >>= 1) mt = fmaxf(mt, __shfl_xor_sync(0xffffffffu, mt, o));
        const float m_new = fmaxf(m_run, mt);
        const float f = __expf(m_run - m_new);
        const float p0 = __expf(s0 - m_new);
        const float p1 = __expf(s1 - m_new);
        float ps = p0 + p1;
#pragma unroll
        for (int o = 16; o; o >>= 1) ps += __shfl_xor_sync(0xffffffffu, ps, o);
        S = S * f + ps;
        m_run = m_new;

        p_buf[w * 68 + l]      = p0;
        p_buf[w * 68 + 32 + l] = p1;
        __syncwarp();

        // ---- PV accumulate: acc(d=2l,2l+1) += p . V_tile ----
        acc.x *= f;
        acc.y *= f;
        const float4* pp = (const float4*)(p_buf + w * 68);
#pragma unroll
        for (int s4 = 0; s4 < 16; s4++) {
            float4 p4 = pp[s4];
#pragma unroll
            for (int r = 0; r < 4; r++) {
                const int s = s4 * 4 + r;
                const float2 vv = *(const float2*)(vb + s * KV_ROW + 2 * l);
                const float pw = ((const float*)&p4)[r];
                acc.x += pw * vv.x;
                acc.y += pw * vv.y;
            }
        }
        __syncthreads();                      // done reading buf c&1
    }

    // ---- epilogue: normalize, bf16 hi/lo split, direct store ----
    const float inv = 1.0f / S;
    const float v0 = acc.x * inv;
    const float v1 = acc.y * inv;
    __nv_bfloat16 h0 = __float2bfloat16(v0);
    __nv_bfloat16 l0 = __float2bfloat16(v0 - __bfloat162float(h0));
    __nv_bfloat16 h1 = __float2bfloat16(v1);
    __nv_bfloat16 l1 = __float2bfloat16(v1 - __bfloat162float(h1));
    const size_t o = ((size_t)(b * NT + w)) * DM + h * DH + 2 * l;
    unsigned hp = (unsigned)__bfloat16_as_ushort(h0) | ((unsigned)__bfloat16_as_ushort(h1) << 16);
    unsigned lp = (unsigned)__bfloat16_as_ushort(l0) | ((unsigned)__bfloat16_as_ushort(l1) << 16);
    *(unsigned*)(g_ah + o) = hp;
    *(unsigned*)(g_al + o) = lp;
}

// =================================================================================
// launch
// =================================================================================
extern "C" void kernel_launch(void* const* d_in, const int* in_sizes, int n_in,
                              void* d_out, int out_size)
{
    const float* x        = (const float*)d_in[0];
    const float* cache_k  = (const float*)d_in[1];
    const float* cache_v  = (const float*)d_in[2];
    const float* Wq       = (const float*)d_in[3];
    const float* bq       = (const float*)d_in[4];
    const float* Wk       = (const float*)d_in[5];
    const float* bk       = (const float*)d_in[6];
    const float* Wv       = (const float*)d_in[7];
    const float* bv       = (const float*)d_in[8];
    const float* Wo       = (const float*)d_in[9];
    const float* bo       = (const float*)d_in[10];
    float*       out      = (float*)d_out;

    static const size_t attn_smem = (size_t)ATTN_SMEM_FLOATS * sizeof(float);
    cudaFuncSetAttribute(attn_kernel, cudaFuncAttributeMaxDynamicSharedMemorySize,
                         (int)attn_smem);

    conv_all<<<1184, 256>>>(Wq, Wk, Wv, Wo, x);

    dim3 gq(4, 96);
    gemm_bf16<0><<<gq, 256>>>(bq, bk, bv);

    attn_kernel<<<NB * NH, 256, attn_smem>>>(cache_k, cache_v);

    dim3 go(4, 32, 2);
    gemm_bf16<1><<<go, 256>>>(nullptr, nullptr, nullptr);

    reduce_bias<<<512, 256>>>(bo, out);
}

// round 11
// speedup vs baseline: 1.1986x; 1.1986x over previous
#include <cuda_runtime.h>
#include <cuda_bf16.h>

#define DM 2048
#define NB 32
#define NT 8
#define NH 32
#define DH 64
#define CT 1016
#define SEQ 1024
#define MROWS 256   // NB*NT

// ---------------- scratch (device globals; no allocation allowed) ----------------
__device__ float g_q   [NB*NH*NT*DH];   // [b][h][t][d]
__device__ float g_kn  [NB*NH*NT*DH];
__device__ float g_vn  [NB*NH*NT*DH];
__device__ float g_part0[MROWS*DM];     // oproj K-split partials
__device__ float g_part1[MROWS*DM];
__device__ float g_part2[MROWS*DM];
__device__ float g_part3[MROWS*DM];

// bf16 hi/lo split scratch
__device__ __align__(16) __nv_bfloat16 g_wqh[DM*DM], g_wql[DM*DM];
__device__ __align__(16) __nv_bfloat16 g_wkh[DM*DM], g_wkl[DM*DM];
__device__ __align__(16) __nv_bfloat16 g_wvh[DM*DM], g_wvl[DM*DM];
__device__ __align__(16) __nv_bfloat16 g_woh[DM*DM], g_wol[DM*DM];
__device__ __align__(16) __nv_bfloat16 g_xh[MROWS*DM], g_xl[MROWS*DM];
__device__ __align__(16) __nv_bfloat16 g_ah[MROWS*DM], g_al[MROWS*DM];  // attn out split

// ---------------- cp.async helpers ----------------
__device__ __forceinline__ void cp16(unsigned dst, const void* src) {
    asm volatile("cp.async.cg.shared.global [%0], [%1], 16;\n" :: "r"(dst), "l"(src));
}
__device__ __forceinline__ void cp_commit() {
    asm volatile("cp.async.commit_group;\n");
}
__device__ __forceinline__ void cp_wait1() {
    asm volatile("cp.async.wait_group 1;\n");
}
__device__ __forceinline__ void cp_wait0() {
    asm volatile("cp.async.wait_group 0;\n");
}

// ---------------- f32x2 packed math ----------------
__device__ __forceinline__ void ffma2(unsigned long long& acc, unsigned long long a,
                                      unsigned long long b) {
    asm("fma.rn.f32x2 %0, %1, %2, %0;" : "+l"(acc) : "l"(a), "l"(b));
}
__device__ __forceinline__ void unpack2(unsigned long long a, float& lo, float& hi) {
    asm("mov.b64 {%0,%1}, %2;" : "=f"(lo), "=f"(hi) : "l"(a));
}
__device__ __forceinline__ unsigned long long pack_dup(float v) {
    unsigned long long r;
    asm("mov.b64 %0, {%1,%1};" : "=l"(r) : "f"(v));
    return r;
}

// ---------------- mma / ldmatrix helpers ----------------
__device__ __forceinline__ void ldm_x4(unsigned addr, unsigned& r0, unsigned& r1,
                                       unsigned& r2, unsigned& r3) {
    asm volatile("ldmatrix.sync.aligned.m8n8.x4.shared.b16 {%0,%1,%2,%3}, [%4];"
                 : "=r"(r0), "=r"(r1), "=r"(r2), "=r"(r3) : "r"(addr));
}
__device__ __forceinline__ void mma16(float* c, const unsigned* a, unsigned b0, unsigned b1) {
    asm volatile(
        "mma.sync.aligned.m16n8k16.row.col.f32.bf16.bf16.f32 "
        "{%0,%1,%2,%3}, {%4,%5,%6,%7}, {%8,%9}, {%0,%1,%2,%3};"
        : "+f"(c[0]), "+f"(c[1]), "+f"(c[2]), "+f"(c[3])
        : "r"(a[0]), "r"(a[1]), "r"(a[2]), "r"(a[3]), "r"(b0), "r"(b1));
}

// =================================================================================
// Prepass: split fp32 -> bf16 hi/lo for 4 weights + x
// =================================================================================
__device__ __forceinline__ void split8_store(const float4 f0, const float4 f1,
                                             __nv_bfloat16* dh, __nv_bfloat16* dl, size_t off) {
    float a[8] = {f0.x, f0.y, f0.z, f0.w, f1.x, f1.y, f1.z, f1.w};
    unsigned short h[8], l[8];
#pragma unroll
    for (int i = 0; i < 8; i++) {
        __nv_bfloat16 hb = __float2bfloat16(a[i]);
        __nv_bfloat16 lb = __float2bfloat16(a[i] - __bfloat162float(hb));
        h[i] = __bfloat16_as_ushort(hb);
        l[i] = __bfloat16_as_ushort(lb);
    }
    uint4 hs, ls;
    hs.x = (unsigned)h[0] | ((unsigned)h[1] << 16);
    hs.y = (unsigned)h[2] | ((unsigned)h[3] << 16);
    hs.z = (unsigned)h[4] | ((unsigned)h[5] << 16);
    hs.w = (unsigned)h[6] | ((unsigned)h[7] << 16);
    ls.x = (unsigned)l[0] | ((unsigned)l[1] << 16);
    ls.y = (unsigned)l[2] | ((unsigned)l[3] << 16);
    ls.z = (unsigned)l[4] | ((unsigned)l[5] << 16);
    ls.w = (unsigned)l[6] | ((unsigned)l[7] << 16);
    ((uint4*)dh)[off] = hs;
    ((uint4*)dl)[off] = ls;
}

#define W8 (DM * DM / 8)
#define X8 (MROWS * DM / 8)

__device__ __forceinline__ void conv_route(int id, const float* wq, const float* wk,
                                           const float* wv, const float* wo, const float* x,
                                           const float*& src, __nv_bfloat16*& dh,
                                           __nv_bfloat16*& dl, int& off) {
    if (id < W8)          { src = wq; dh = g_wqh; dl = g_wql; off = id; }
    else if (id < 2 * W8) { src = wk; dh = g_wkh; dl = g_wkl; off = id - W8; }
    else if (id < 3 * W8) { src = wv; dh = g_wvh; dl = g_wvl; off = id - 2 * W8; }
    else if (id < 4 * W8) { src = wo; dh = g_woh; dl = g_wol; off = id - 3 * W8; }
    else                  { src = x;  dh = g_xh;  dl = g_xl;  off = id - 4 * W8; }
}

__global__ __launch_bounds__(256) void conv_all(
    const float* __restrict__ wq, const float* __restrict__ wk,
    const float* __restrict__ wv, const float* __restrict__ wo,
    const float* __restrict__ x)
{
    const int total = 4 * W8 + X8;
    for (int id = blockIdx.x * 512 + threadIdx.x; id < total; id += gridDim.x * 512) {
        const int id2 = id + 256;
        const float *s0, *s1 = nullptr; __nv_bfloat16 *h0, *l0, *h1, *l1; int o0, o1;
        conv_route(id, wq, wk, wv, wo, x, s0, h0, l0, o0);
        float4 a0 = ((const float4*)s0)[(size_t)o0 * 2];
        float4 a1 = ((const float4*)s0)[(size_t)o0 * 2 + 1];
        float4 b0, b1;
        if (id2 < total) {
            conv_route(id2, wq, wk, wv, wo, x, s1, h1, l1, o1);
            b0 = ((const float4*)s1)[(size_t)o1 * 2];
            b1 = ((const float4*)s1)[(size_t)o1 * 2 + 1];
        }
        split8_store(a0, a1, h0, l0, o0);
        if (id2 < total) split8_store(b0, b1, h1, l1, o1);
    }
}

// =================================================================================
// bf16-split GEMM (3xBF16), BM=64 BN=64 BK=32, 256 thr.
// MODE 0: QKV full-K -> g_q/g_kn/g_vn (+bias).  MODE 1: O-proj 4-way K-split.
// =================================================================================
template<int MODE>
__global__ __launch_bounds__(256) void gemm_bf16(
    const float* __restrict__ bi0, const float* __restrict__ bi1,
    const float* __restrict__ bi2)
{
    __shared__ __align__(16) unsigned char smem[2 * 16384];

    const int tid  = threadIdx.x;
    const int lane = tid & 31;
    const int wid  = tid >> 5;
    const int gid  = lane >> 2;
    const int tig  = lane & 3;
    const int wm   = wid & 1;
    const int wn   = wid >> 1;
    const int bx = blockIdx.x;
    const int by = blockIdx.y;
    const int bz = blockIdx.z;

    const __nv_bfloat16 *Ah, *Al, *Bh, *Bl;
    const float* bsel = nullptr;
    float* dst = nullptr;
    float* pOut = nullptr;
    int nrow0;
    int it0, it1;
    if (MODE == 0) {
        const int type = by >> 5;
        Ah = g_xh; Al = g_xl;
        Bh = (type == 0) ? g_wqh : (type == 1) ? g_wkh : g_wvh;
        Bl = (type == 0) ? g_wql : (type == 1) ? g_wkl : g_wvl;
        bsel = (type == 0) ? bi0 : (type == 1) ? bi1 : bi2;
        dst  = (type == 0) ? g_q : (type == 1) ? g_kn : g_vn;
        nrow0 = (by & 31) * 64;
        it0 = 0; it1 = DM / 32;
    } else {
        Ah = g_ah; Al = g_al; Bh = g_woh; Bl = g_wol;
        pOut = (bz == 0) ? g_part0 : (bz == 1) ? g_part1 : (bz == 2) ? g_part2 : g_part3;
        nrow0 = by * 64;
        it0 = bz * (DM / 128); it1 = it0 + DM / 128;
    }
    const int row0 = bx * 64;

    const unsigned sbase = (unsigned)__cvta_generic_to_shared(smem);

    const int sr = tid >> 2;
    const int sc = tid & 3;
    const unsigned sdst = sbase + (unsigned)(sr * 64 + (sc ^ ((sr >> 1) & 3)) * 16);
    const __nv_bfloat16* aSrc  = Ah + (size_t)(row0  + sr) * DM + sc * 8;
    const __nv_bfloat16* alSrc = Al + (size_t)(row0  + sr) * DM + sc * 8;
    const __nv_bfloat16* bSrc  = Bh + (size_t)(nrow0 + sr) * DM + sc * 8;
    const __nv_bfloat16* blSrc = Bl + (size_t)(nrow0 + sr) * DM + sc * 8;

    float acc[2][2][4];
#pragma unroll
    for (int i = 0; i < 2; i++)
#pragma unroll
        for (int j = 0; j < 2; j++)
#pragma unroll
            for (int q = 0; q < 4; q++) acc[i][j][q] = 0.f;

    const int a_l15 = lane & 15;
    const int ku_a  = lane >> 4;
    const int brow  = wn * 16 + ((lane & 7) | ((lane & 16) >> 1));
    const int ku_b  = (lane >> 3) & 1;

    {
        const int ko = it0 * 32;
        cp16(sdst,          aSrc  + ko);
        cp16(sdst + 4096u,  alSrc + ko);
        cp16(sdst + 8192u,  bSrc  + ko);
        cp16(sdst + 12288u, blSrc + ko);
        cp_commit();
    }

    for (int it = it0; it < it1; ++it) {
        if (it < it1 - 1) {
            const int ko = (it + 1) * 32;
            const unsigned d = sdst + (unsigned)(((it - it0 + 1) & 1) * 16384);
            cp16(d,          aSrc  + ko);
            cp16(d + 4096u,  alSrc + ko);
            cp16(d + 8192u,  bSrc  + ko);
            cp16(d + 12288u, blSrc + ko);
            cp_commit();
            cp_wait1();
        } else {
            cp_wait0();
        }
        __syncthreads();

        const unsigned sb = sbase + (unsigned)(((it - it0) & 1) * 16384);
#pragma unroll
        for (int ks = 0; ks < 2; ks++) {
            unsigned ah[2][4], al_[2][4], bh[4], bl[4];
#pragma unroll
            for (int i = 0; i < 2; i++) {
                const int r  = wm * 32 + i * 16 + a_l15;
                const int pu = (ks * 2 + ku_a) ^ ((r >> 1) & 3);
                const unsigned ad = sb + (unsigned)(r * 64 + pu * 16);
                ldm_x4(ad,         ah[i][0],  ah[i][1],  ah[i][2],  ah[i][3]);
                ldm_x4(ad + 4096u, al_[i][0], al_[i][1], al_[i][2], al_[i][3]);
            }
            {
                const int pu = (ks * 2 + ku_b) ^ ((brow >> 1) & 3);
                const unsigned bd = sb + 8192u + (unsigned)(brow * 64 + pu * 16);
                ldm_x4(bd,         bh[0], bh[1], bh[2], bh[3]);
                ldm_x4(bd + 4096u, bl[0], bl[1], bl[2], bl[3]);
            }
#pragma unroll
            for (int i = 0; i < 2; i++)
#pragma unroll
                for (int j = 0; j < 2; j++) {
                    mma16(acc[i][j], ah[i],  bh[2 * j], bh[2 * j + 1]);
                    mma16(acc[i][j], ah[i],  bl[2 * j], bl[2 * j + 1]);
                    mma16(acc[i][j], al_[i], bh[2 * j], bh[2 * j + 1]);
                }
        }
        __syncthreads();
    }

#pragma unroll
    for (int i = 0; i < 2; i++) {
#pragma unroll
        for (int j = 0; j < 2; j++) {
#pragma unroll
            for (int q = 0; q < 4; q++) {
                const int m = row0 + wm * 32 + i * 16 + gid + ((q >= 2) ? 8 : 0);
                const int n = nrow0 + wn * 16 + j * 8 + 2 * tig + (q & 1);
                if (MODE == 0) {
                    const float v = acc[i][j][q] + bsel[n];
                    const int h = n >> 6, d = n & 63;
                    const int bb = m >> 3, tt = m & 7;
                    dst[(((size_t)(bb * NH + h)) * NT + tt) * DH + d] = v;
                } else {
                    pOut[(size_t)m * DM + n] = acc[i][j][q];
                }
            }
        }
    }
}

// oproj partial reduce + bias -> out  (4-way)
__global__ __launch_bounds__(256) void reduce_bias(
    const float* __restrict__ bo, float* __restrict__ out)
{
    const int i = blockIdx.x * 256 + threadIdx.x;
    float4 a = ((const float4*)g_part0)[i];
    float4 b = ((const float4*)g_part1)[i];
    float4 c = ((const float4*)g_part2)[i];
    float4 d = ((const float4*)g_part3)[i];
    const int n4 = (i & (DM / 4 - 1)) * 4;
    float4 bb = *(const float4*)(bo + n4);
    float4 r;
    r.x = ((a.x + b.x) + (c.x + d.x)) + bb.x;
    r.y = ((a.y + b.y) + (c.y + d.y)) + bb.y;
    r.z = ((a.z + b.z) + (c.z + d.z)) + bb.z;
    r.w = ((a.w + b.w) + (c.w + d.w)) + bb.w;
    ((float4*)out)[i] = r;
}

// =================================================================================
// Attention per (b,h). 1024 blocks x 256 threads. R7 structure, FFMA2 compute.
// smem: q[512] | p[8192] | kv[2][64*68] | unused[8]
// =================================================================================
#define KV_ROW 68
#define KV_TILE (64 * KV_ROW)
#define ATTN_SMEM_FLOATS (512 + 8192 + 2 * KV_TILE + 8)

__device__ __forceinline__ void stage_tile(unsigned kv_smem_addr, int buf, int tile, int tid,
                                           const float* __restrict__ cache,
                                           const float* __restrict__ newer)
{
#pragma unroll
    for (int i = 0; i < 4; i++) {
        const int idx = tid + i * 256;
        const int sl  = idx >> 4;
        const int c4  = idx & 15;
        const int s   = tile * 64 + sl;
        const float* src = (s < CT) ? (cache + (size_t)s * DH + c4 * 4)
                                    : (newer + (size_t)(s - CT) * DH + c4 * 4);
        const unsigned dstoff = (unsigned)((buf * KV_TILE + sl * KV_ROW + c4 * 4) * 4);
        cp16(kv_smem_addr + dstoff, src);
    }
    cp_commit();
}

__global__ __launch_bounds__(256) void attn_kernel(
    const float* __restrict__ cache_k,
    const float* __restrict__ cache_v)
{
    extern __shared__ float sm[];
    float* q_s     = sm;
    float* p       = sm + 512;
    float* kv      = p + 8192;

    const int tid = threadIdx.x;
    const int w   = tid >> 5;
    const int l   = tid & 31;
    const int bh  = blockIdx.x;
    const int b   = bh >> 5;
    const int h   = bh & 31;

    const float* qsrc = g_q + (size_t)bh * (NT * DH);
    q_s[tid]       = qsrc[tid]       * 0.125f;
    q_s[tid + 256] = qsrc[tid + 256] * 0.125f;

    const float* ck = cache_k + (size_t)bh * CT * DH;
    const float* cv = cache_v + (size_t)bh * CT * DH;
    const float* kn = g_kn + (size_t)bh * (NT * DH);
    const float* vn = g_vn + (size_t)bh * (NT * DH);

    const unsigned kv_addr = (unsigned)__cvta_generic_to_shared(kv);

    // ---------------- Pass 1: scores = q @ K^T (FFMA2 over d-pairs) ----------------
    stage_tile(kv_addr, 0, 0, tid, ck, kn);
    for (int c = 0; c < 16; c++) {
        if (c < 15) { stage_tile(kv_addr, (c + 1) & 1, c + 1, tid, ck, kn); cp_wait1(); }
        else        { cp_wait0(); }
        __syncthreads();

        const float* kb = kv + (c & 1) * KV_TILE;
        const int g  = tid >> 6;
        const int sl = tid & 63;
        const int t0 = g * 2, t1 = g * 2 + 1;
        const ulonglong2* krow = (const ulonglong2*)(kb + sl * KV_ROW);
        const ulonglong2* q0   = (const ulonglong2*)(q_s + t0 * DH);
        const ulonglong2* q1   = (const ulonglong2*)(q_s + t1 * DH);

        unsigned long long a00 = 0ull, a01 = 0ull, a10 = 0ull, a11 = 0ull;
#pragma unroll
        for (int i = 0; i < 16; i++) {
            ulonglong2 kk = krow[i];
            ulonglong2 qa = q0[i];
            ulonglong2 qb = q1[i];
            ffma2(a00, kk.x, qa.x);
            ffma2(a01, kk.y, qa.y);
            ffma2(a10, kk.x, qb.x);
            ffma2(a11, kk.y, qb.y);
        }
        float x0, x1, y0, y1, z0, z1, u0, u1;
        unpack2(a00, x0, x1); unpack2(a01, y0, y1);
        unpack2(a10, z0, z1); unpack2(a11, u0, u1);
        const int s = c * 64 + sl;
        p[t0 * SEQ + s] = (x0 + x1) + (y0 + y1);
        p[t1 * SEQ + s] = (z0 + z1) + (u0 + u1);
        __syncthreads();
    }

    stage_tile(kv_addr, 0, 0, tid, cv, vn);

    // ---------------- softmax: warp w owns row t=w ----------------
    float inv_w;
    {
        float* pr = p + w * SEQ;
        float mx = -1e30f;
        for (int i = l; i < SEQ; i += 32) mx = fmaxf(mx, pr[i]);
#pragma unroll
        for (int o = 16; o; o >>= 1) mx = fmaxf(mx, __shfl_xor_sync(0xffffffffu, mx, o));
        float sum = 0.f;
        for (int i = l; i < SEQ; i += 32) {
            float e = __expf(pr[i] - mx);
            pr[i] = e;
            sum += e;
        }
#pragma unroll
        for (int o = 16; o; o >>= 1) sum += __shfl_xor_sync(0xffffffffu, sum, o);
        inv_w = 1.0f / sum;   // valid in all lanes after xor-reduce
    }
    __syncthreads();

    // ---------------- Pass 2: out = p @ V (FFMA2, lane owns d-pair 2l,2l+1) -------
    unsigned long long accp[8];
#pragma unroll
    for (int t = 0; t < 8; t++) accp[t] = 0ull;

    for (int c = 0; c < 16; c++) {
        if (c < 15) { stage_tile(kv_addr, (c + 1) & 1, c + 1, tid, cv, vn); cp_wait1(); }
        else        { cp_wait0(); }
        __syncthreads();

        const float* vb = kv + (c & 1) * KV_TILE;
#pragma unroll
        for (int half = 0; half < 2; half++) {
            float4 pt[8];
#pragma unroll
            for (int t = 0; t < 8; t++)
                pt[t] = *(const float4*)(p + t * SEQ + c * 64 + w * 8 + half * 4);
#pragma unroll
            for (int r2 = 0; r2 < 4; r2++) {
                const int sl = w * 8 + half * 4 + r2;
                const unsigned long long vv = *(const unsigned long long*)(vb + sl * KV_ROW + 2 * l);
#pragma unroll
                for (int t = 0; t < 8; t++) {
                    const float pw = ((const float*)&pt[t])[r2];
                    ffma2(accp[t], vv, pack_dup(pw));
                }
            }
        }
        __syncthreads();
    }

    // ---------------- cross-warp reduce (reuse p as 8x512 scratch) ----------------
    // store inv_sum per row into q_s area (q no longer needed)
    if (l == 0) q_s[w] = inv_w;
    float* red = p;
#pragma unroll
    for (int t = 0; t < 8; t++) {
        float e0, e1;
        unpack2(accp[t], e0, e1);
        *(float2*)(red + w * 512 + t * 64 + 2 * l) = make_float2(e0, e1);
    }
    __syncthreads();
    for (int i = tid; i < 512; i += 256) {
        float ssum = 0.f;
#pragma unroll
        for (int ww = 0; ww < 8; ww++) ssum += red[ww * 512 + i];
        const int t = i >> 6, d = i & 63;
        const float val = ssum * q_s[t];
        __nv_bfloat16 hb2 = __float2bfloat16(val);
        __nv_bfloat16 lb2 = __float2bfloat16(val - __bfloat162float(hb2));
        const size_t o = ((size_t)(b * NT + t)) * DM + h * DH + d;
        g_ah[o] = hb2;
        g_al[o] = lb2;
    }
}

// =================================================================================
// launch
// =================================================================================
extern "C" void kernel_launch(void* const* d_in, const int* in_sizes, int n_in,
                              void* d_out, int out_size)
{
    const float* x        = (const float*)d_in[0];
    const float* cache_k  = (const float*)d_in[1];
    const float* cache_v  = (const float*)d_in[2];
    const float* Wq       = (const float*)d_in[3];
    const float* bq       = (const float*)d_in[4];
    const float* Wk       = (const float*)d_in[5];
    const float* bk       = (const float*)d_in[6];
    const float* Wv       = (const float*)d_in[7];
    const float* bv       = (const float*)d_in[8];
    const float* Wo       = (const float*)d_in[9];
    const float* bo       = (const float*)d_in[10];
    float*       out      = (float*)d_out;

    static const size_t attn_smem = (size_t)ATTN_SMEM_FLOATS * sizeof(float);
    cudaFuncSetAttribute(attn_kernel, cudaFuncAttributeMaxDynamicSharedMemorySize,
                         (int)attn_smem);

    conv_all<<<1184, 256>>>(Wq, Wk, Wv, Wo, x);

    dim3 gq(4, 96);
    gemm_bf16<0><<<gq, 256>>>(bq, bk, bv);

    attn_kernel<<<NB * NH, 256, attn_smem>>>(cache_k, cache_v);

    dim3 go(4, 32, 4);
    gemm_bf16<1><<<go, 256>>>(nullptr, nullptr, nullptr);

    reduce_bias<<<512, 256>>>(bo, out);
}

// round 13
// speedup vs baseline: 1.2217x; 1.0193x over previous
#include <cuda_runtime.h>
#include <cuda_bf16.h>

#define DM 2048
#define NB 32
#define NT 8
#define NH 32
#define DH 64
#define CT 1016
#define SEQ 1024
#define MROWS 256   // NB*NT

// ---------------- scratch (device globals; no allocation allowed) ----------------
__device__ float g_q   [NB*NH*NT*DH];   // [b][h][t][d]
__device__ float g_kn  [NB*NH*NT*DH];
__device__ float g_vn  [NB*NH*NT*DH];
__device__ float g_part0[MROWS*DM];     // oproj K-split partials
__device__ float g_part1[MROWS*DM];
__device__ float g_part2[MROWS*DM];
__device__ float g_part3[MROWS*DM];

// bf16 hi/lo split scratch
__device__ __align__(16) __nv_bfloat16 g_wqh[DM*DM], g_wql[DM*DM];
__device__ __align__(16) __nv_bfloat16 g_wkh[DM*DM], g_wkl[DM*DM];
__device__ __align__(16) __nv_bfloat16 g_wvh[DM*DM], g_wvl[DM*DM];
__device__ __align__(16) __nv_bfloat16 g_woh[DM*DM], g_wol[DM*DM];
__device__ __align__(16) __nv_bfloat16 g_xh[MROWS*DM], g_xl[MROWS*DM];
__device__ __align__(16) __nv_bfloat16 g_ah[MROWS*DM], g_al[MROWS*DM];  // attn out split

// ---------------- cp.async helpers ----------------
__device__ __forceinline__ void cp16(unsigned dst, const void* src) {
    asm volatile("cp.async.cg.shared.global [%0], [%1], 16;\n" :: "r"(dst), "l"(src));
}
__device__ __forceinline__ void cp_commit() {
    asm volatile("cp.async.commit_group;\n");
}
__device__ __forceinline__ void cp_wait1() {
    asm volatile("cp.async.wait_group 1;\n");
}
__device__ __forceinline__ void cp_wait0() {
    asm volatile("cp.async.wait_group 0;\n");
}

// ---------------- mma / ldmatrix helpers ----------------
__device__ __forceinline__ void ldm_x4(unsigned addr, unsigned& r0, unsigned& r1,
                                       unsigned& r2, unsigned& r3) {
    asm volatile("ldmatrix.sync.aligned.m8n8.x4.shared.b16 {%0,%1,%2,%3}, [%4];"
                 : "=r"(r0), "=r"(r1), "=r"(r2), "=r"(r3) : "r"(addr));
}
__device__ __forceinline__ void mma16(float* c, const unsigned* a, unsigned b0, unsigned b1) {
    asm volatile(
        "mma.sync.aligned.m16n8k16.row.col.f32.bf16.bf16.f32 "
        "{%0,%1,%2,%3}, {%4,%5,%6,%7}, {%8,%9}, {%0,%1,%2,%3};"
        : "+f"(c[0]), "+f"(c[1]), "+f"(c[2]), "+f"(c[3])
        : "r"(a[0]), "r"(a[1]), "r"(a[2]), "r"(a[3]), "r"(b0), "r"(b1));
}

// =================================================================================
// Prepass: split fp32 -> bf16 hi/lo, batch-4 front-loaded (MLP ~8)
// total chunks = 4*W8 + X8 = 2162688; grid 2112 x 256 thr x 4 chunks = exact cover
// =================================================================================
__device__ __forceinline__ void split8_store(const float4 f0, const float4 f1,
                                             __nv_bfloat16* dh, __nv_bfloat16* dl, size_t off) {
    float a[8] = {f0.x, f0.y, f0.z, f0.w, f1.x, f1.y, f1.z, f1.w};
    unsigned short h[8], l[8];
#pragma unroll
    for (int i = 0; i < 8; i++) {
        __nv_bfloat16 hb = __float2bfloat16(a[i]);
        __nv_bfloat16 lb = __float2bfloat16(a[i] - __bfloat162float(hb));
        h[i] = __bfloat16_as_ushort(hb);
        l[i] = __bfloat16_as_ushort(lb);
    }
    uint4 hs, ls;
    hs.x = (unsigned)h[0] | ((unsigned)h[1] << 16);
    hs.y = (unsigned)h[2] | ((unsigned)h[3] << 16);
    hs.z = (unsigned)h[4] | ((unsigned)h[5] << 16);
    hs.w = (unsigned)h[6] | ((unsigned)h[7] << 16);
    ls.x = (unsigned)l[0] | ((unsigned)l[1] << 16);
    ls.y = (unsigned)l[2] | ((unsigned)l[3] << 16);
    ls.z = (unsigned)l[4] | ((unsigned)l[5] << 16);
    ls.w = (unsigned)l[6] | ((unsigned)l[7] << 16);
    ((uint4*)dh)[off] = hs;
    ((uint4*)dl)[off] = ls;
}

#define W8 (DM * DM / 8)
#define X8 (MROWS * DM / 8)

__device__ __forceinline__ void conv_route(int id, const float* wq, const float* wk,
                                           const float* wv, const float* wo, const float* x,
                                           const float*& src, __nv_bfloat16*& dh,
                                           __nv_bfloat16*& dl, int& off) {
    if (id < W8)          { src = wq; dh = g_wqh; dl = g_wql; off = id; }
    else if (id < 2 * W8) { src = wk; dh = g_wkh; dl = g_wkl; off = id - W8; }
    else if (id < 3 * W8) { src = wv; dh = g_wvh; dl = g_wvl; off = id - 2 * W8; }
    else if (id < 4 * W8) { src = wo; dh = g_woh; dl = g_wol; off = id - 3 * W8; }
    else                  { src = x;  dh = g_xh;  dl = g_xl;  off = id - 4 * W8; }
}

__global__ __launch_bounds__(256) void conv_all(
    const float* __restrict__ wq, const float* __restrict__ wk,
    const float* __restrict__ wv, const float* __restrict__ wo,
    const float* __restrict__ x)
{
    const int base = blockIdx.x * 1024 + threadIdx.x;
    const float* s[4]; __nv_bfloat16 *dh[4], *dl[4]; int of[4];
    float4 f0[4], f1[4];
#pragma unroll
    for (int k = 0; k < 4; k++) {
        conv_route(base + k * 256, wq, wk, wv, wo, x, s[k], dh[k], dl[k], of[k]);
        f0[k] = ((const float4*)s[k])[(size_t)of[k] * 2];
        f1[k] = ((const float4*)s[k])[(size_t)of[k] * 2 + 1];
    }
#pragma unroll
    for (int k = 0; k < 4; k++)
        split8_store(f0[k], f1[k], dh[k], dl[k], of[k]);
}

// =================================================================================
// bf16-split GEMM (3xBF16), BM=64 BN=64 BK=32, 256 thr.
// Split accumulators: acc (hh chain) + accc (hl+lh corrections) -> 8 indep chains.
// MODE 0: QKV full-K -> g_q/g_kn/g_vn (+bias).  MODE 1: O-proj 4-way K-split.
// =================================================================================
template<int MODE>
__global__ __launch_bounds__(256) void gemm_bf16(
    const float* __restrict__ bi0, const float* __restrict__ bi1,
    const float* __restrict__ bi2)
{
    __shared__ __align__(16) unsigned char smem[2 * 16384];

    const int tid  = threadIdx.x;
    const int lane = tid & 31;
    const int wid  = tid >> 5;
    const int gid  = lane >> 2;
    const int tig  = lane & 3;
    const int wm   = wid & 1;
    const int wn   = wid >> 1;
    const int bx = blockIdx.x;
    const int by = blockIdx.y;
    const int bz = blockIdx.z;

    const __nv_bfloat16 *Ah, *Al, *Bh, *Bl;
    const float* bsel = nullptr;
    float* dst = nullptr;
    float* pOut = nullptr;
    int nrow0;
    int it0, it1;
    if (MODE == 0) {
        const int type = by >> 5;
        Ah = g_xh; Al = g_xl;
        Bh = (type == 0) ? g_wqh : (type == 1) ? g_wkh : g_wvh;
        Bl = (type == 0) ? g_wql : (type == 1) ? g_wkl : g_wvl;
        bsel = (type == 0) ? bi0 : (type == 1) ? bi1 : bi2;
        dst  = (type == 0) ? g_q : (type == 1) ? g_kn : g_vn;
        nrow0 = (by & 31) * 64;
        it0 = 0; it1 = DM / 32;
    } else {
        Ah = g_ah; Al = g_al; Bh = g_woh; Bl = g_wol;
        pOut = (bz == 0) ? g_part0 : (bz == 1) ? g_part1 : (bz == 2) ? g_part2 : g_part3;
        nrow0 = by * 64;
        it0 = bz * (DM / 128); it1 = it0 + DM / 128;
    }
    const int row0 = bx * 64;

    const unsigned sbase = (unsigned)__cvta_generic_to_shared(smem);

    const int sr = tid >> 2;
    const int sc = tid & 3;
    const unsigned sdst = sbase + (unsigned)(sr * 64 + (sc ^ ((sr >> 1) & 3)) * 16);
    const __nv_bfloat16* aSrc  = Ah + (size_t)(row0  + sr) * DM + sc * 8;
    const __nv_bfloat16* alSrc = Al + (size_t)(row0  + sr) * DM + sc * 8;
    const __nv_bfloat16* bSrc  = Bh + (size_t)(nrow0 + sr) * DM + sc * 8;
    const __nv_bfloat16* blSrc = Bl + (size_t)(nrow0 + sr) * DM + sc * 8;

    float acc[2][2][4];    // hh chains
    float accc[2][2][4];   // correction chains (hl + lh)
#pragma unroll
    for (int i = 0; i < 2; i++)
#pragma unroll
        for (int j = 0; j < 2; j++)
#pragma unroll
            for (int q = 0; q < 4; q++) { acc[i][j][q] = 0.f; accc[i][j][q] = 0.f; }

    const int a_l15 = lane & 15;
    const int ku_a  = lane >> 4;
    const int brow  = wn * 16 + ((lane & 7) | ((lane & 16) >> 1));
    const int ku_b  = (lane >> 3) & 1;

    {
        const int ko = it0 * 32;
        cp16(sdst,          aSrc  + ko);
        cp16(sdst + 4096u,  alSrc + ko);
        cp16(sdst + 8192u,  bSrc  + ko);
        cp16(sdst + 12288u, blSrc + ko);
        cp_commit();
    }

    for (int it = it0; it < it1; ++it) {
        if (it < it1 - 1) {
            const int ko = (it + 1) * 32;
            const unsigned d = sdst + (unsigned)(((it - it0 + 1) & 1) * 16384);
            cp16(d,          aSrc  + ko);
            cp16(d + 4096u,  alSrc + ko);
            cp16(d + 8192u,  bSrc  + ko);
            cp16(d + 12288u, blSrc + ko);
            cp_commit();
            cp_wait1();
        } else {
            cp_wait0();
        }
        __syncthreads();

        const unsigned sb = sbase + (unsigned)(((it - it0) & 1) * 16384);
#pragma unroll
        for (int ks = 0; ks < 2; ks++) {
            unsigned ah[2][4], al_[2][4], bh[4], bl[4];
#pragma unroll
            for (int i = 0; i < 2; i++) {
                const int r  = wm * 32 + i * 16 + a_l15;
                const int pu = (ks * 2 + ku_a) ^ ((r >> 1) & 3);
                const unsigned ad = sb + (unsigned)(r * 64 + pu * 16);
                ldm_x4(ad,         ah[i][0],  ah[i][1],  ah[i][2],  ah[i][3]);
                ldm_x4(ad + 4096u, al_[i][0], al_[i][1], al_[i][2], al_[i][3]);
            }
            {
                const int pu = (ks * 2 + ku_b) ^ ((brow >> 1) & 3);
                const unsigned bd = sb + 8192u + (unsigned)(brow * 64 + pu * 16);
                ldm_x4(bd,         bh[0], bh[1], bh[2], bh[3]);
                ldm_x4(bd + 4096u, bl[0], bl[1], bl[2], bl[3]);
            }
#pragma unroll
            for (int i = 0; i < 2; i++)
#pragma unroll
                for (int j = 0; j < 2; j++) {
                    mma16(acc[i][j],  ah[i],  bh[2 * j], bh[2 * j + 1]);   // hh chain
                    mma16(accc[i][j], ah[i],  bl[2 * j], bl[2 * j + 1]);   // corr chain
                    mma16(accc[i][j], al_[i], bh[2 * j], bh[2 * j + 1]);   // corr chain
                }
        }
        __syncthreads();
    }

#pragma unroll
    for (int i = 0; i < 2; i++) {
#pragma unroll
        for (int j = 0; j < 2; j++) {
#pragma unroll
            for (int q = 0; q < 4; q++) {
                const int m = row0 + wm * 32 + i * 16 + gid + ((q >= 2) ? 8 : 0);
                const int n = nrow0 + wn * 16 + j * 8 + 2 * tig + (q & 1);
                const float sumv = acc[i][j][q] + accc[i][j][q];
                if (MODE == 0) {
                    const float v = sumv + bsel[n];
                    const int h = n >> 6, d = n & 63;
                    const int bb = m >> 3, tt = m & 7;
                    dst[(((size_t)(bb * NH + h)) * NT + tt) * DH + d] = v;
                } else {
                    pOut[(size_t)m * DM + n] = sumv;
                }
            }
        }
    }
}

// oproj partial reduce + bias -> out  (4-way)
__global__ __launch_bounds__(256) void reduce_bias(
    const float* __restrict__ bo, float* __restrict__ out)
{
    const int i = blockIdx.x * 256 + threadIdx.x;
    float4 a = ((const float4*)g_part0)[i];
    float4 b = ((const float4*)g_part1)[i];
    float4 c = ((const float4*)g_part2)[i];
    float4 d = ((const float4*)g_part3)[i];
    const int n4 = (i & (DM / 4 - 1)) * 4;
    float4 bb = *(const float4*)(bo + n4);
    float4 r;
    r.x = ((a.x + b.x) + (c.x + d.x)) + bb.x;
    r.y = ((a.y + b.y) + (c.y + d.y)) + bb.y;
    r.z = ((a.z + b.z) + (c.z + d.z)) + bb.z;
    r.w = ((a.w + b.w) + (c.w + d.w)) + bb.w;
    ((float4*)out)[i] = r;
}

// =================================================================================
// Attention per (b,h). 1024 blocks x 256 threads. (R7 structure — best known)
// =================================================================================
#define KV_ROW 68
#define KV_TILE (64 * KV_ROW)
#define ATTN_SMEM_FLOATS (512 + 8192 + 2 * KV_TILE + 8)

__device__ __forceinline__ void stage_tile(unsigned kv_smem_addr, int buf, int tile, int tid,
                                           const float* __restrict__ cache,
                                           const float* __restrict__ newer)
{
#pragma unroll
    for (int i = 0; i < 4; i++) {
        const int idx = tid + i * 256;
        const int sl  = idx >> 4;
        const int c4  = idx & 15;
        const int s   = tile * 64 + sl;
        const float* src = (s < CT) ? (cache + (size_t)s * DH + c4 * 4)
                                    : (newer + (size_t)(s - CT) * DH + c4 * 4);
        const unsigned dstoff = (unsigned)((buf * KV_TILE + sl * KV_ROW + c4 * 4) * 4);
        cp16(kv_smem_addr + dstoff, src);
    }
    cp_commit();
}

__global__ __launch_bounds__(256) void attn_kernel(
    const float* __restrict__ cache_k,
    const float* __restrict__ cache_v)
{
    extern __shared__ float sm[];
    float* q_s     = sm;
    float* p       = sm + 512;
    float* kv      = p + 8192;
    float* inv_sum = kv + 2 * KV_TILE;

    const int tid = threadIdx.x;
    const int w   = tid >> 5;
    const int l   = tid & 31;
    const int bh  = blockIdx.x;
    const int b   = bh >> 5;
    const int h   = bh & 31;

    const float* qsrc = g_q + (size_t)bh * (NT * DH);
    q_s[tid]       = qsrc[tid]       * 0.125f;
    q_s[tid + 256] = qsrc[tid + 256] * 0.125f;

    const float* ck = cache_k + (size_t)bh * CT * DH;
    const float* cv = cache_v + (size_t)bh * CT * DH;
    const float* kn = g_kn + (size_t)bh * (NT * DH);
    const float* vn = g_vn + (size_t)bh * (NT * DH);

    const unsigned kv_addr = (unsigned)__cvta_generic_to_shared(kv);

    // Pass 1: scores = q @ K^T
    stage_tile(kv_addr, 0, 0, tid, ck, kn);
    for (int c = 0; c < 16; c++) {
        if (c < 15) { stage_tile(kv_addr, (c + 1) & 1, c + 1, tid, ck, kn); cp_wait1(); }
        else        { cp_wait0(); }
        __syncthreads();

        const float* kb = kv + (c & 1) * KV_TILE;
        const int g  = tid >> 6;
        const int sl = tid & 63;
        const int t0 = g * 2, t1 = g * 2 + 1;
        float a0 = 0.f, a1 = 0.f;
        const float4* krow = (const float4*)(kb + sl * KV_ROW);
        const float4* q0   = (const float4*)(q_s + t0 * DH);
        const float4* q1   = (const float4*)(q_s + t1 * DH);
#pragma unroll
        for (int c4 = 0; c4 < 16; c4++) {
            float4 kk = krow[c4];
            float4 qa = q0[c4], qb = q1[c4];
            a0 += kk.x * qa.x + kk.y * qa.y + kk.z * qa.z + kk.w * qa.w;
            a1 += kk.x * qb.x + kk.y * qb.y + kk.z * qb.z + kk.w * qb.w;
        }
        const int s = c * 64 + sl;
        p[t0 * SEQ + s] = a0;
        p[t1 * SEQ + s] = a1;
        __syncthreads();
    }

    stage_tile(kv_addr, 0, 0, tid, cv, vn);

    // softmax
    {
        float* pr = p + w * SEQ;
        float mx = -1e30f;
        for (int i = l; i < SEQ; i += 32) mx = fmaxf(mx, pr[i]);
#pragma unroll
        for (int o = 16; o; o >>= 1) mx = fmaxf(mx, __shfl_xor_sync(0xffffffffu, mx, o));
        float sum = 0.f;
        for (int i = l; i < SEQ; i += 32) {
            float e = __expf(pr[i] - mx);
            pr[i] = e;
            sum += e;
        }
#pragma unroll
        for (int o = 16; o; o >>= 1) sum += __shfl_xor_sync(0xffffffffu, sum, o);
        if (l == 0) inv_sum[w] = 1.0f / sum;
    }
    __syncthreads();

    // Pass 2: out = p @ V
    float acc[8][2];
#pragma unroll
    for (int t = 0; t < 8; t++) { acc[t][0] = 0.f; acc[t][1] = 0.f; }

    for (int c = 0; c < 16; c++) {
        if (c < 15) { stage_tile(kv_addr, (c + 1) & 1, c + 1, tid, cv, vn); cp_wait1(); }
        else        { cp_wait0(); }
        __syncthreads();

        const float* vb = kv + (c & 1) * KV_TILE;
#pragma unroll
        for (int r = 0; r < 8; r++) {
            const int sl = w * 8 + r;
            const float v0 = vb[sl * KV_ROW + l];
            const float v1 = vb[sl * KV_ROW + 32 + l];
            const int s = c * 64 + sl;
#pragma unroll
            for (int t = 0; t < 8; t++) {
                const float pw = p[t * SEQ + s];
                acc[t][0] += pw * v0;
                acc[t][1] += pw * v1;
            }
        }
        __syncthreads();
    }

    float* red = p;
#pragma unroll
    for (int t = 0; t < 8; t++) {
        red[w * 512 + t * 64 + l]      = acc[t][0];
        red[w * 512 + t * 64 + 32 + l] = acc[t][1];
    }
    __syncthreads();
    for (int i = tid; i < 512; i += 256) {
        float ssum = 0.f;
#pragma unroll
        for (int ww = 0; ww < 8; ww++) ssum += red[ww * 512 + i];
        const int t = i >> 6, d = i & 63;
        const float val = ssum * inv_sum[t];
        __nv_bfloat16 hb2 = __float2bfloat16(val);
        __nv_bfloat16 lb2 = __float2bfloat16(val - __bfloat162float(hb2));
        const size_t o = ((size_t)(b * NT + t)) * DM + h * DH + d;
        g_ah[o] = hb2;
        g_al[o] = lb2;
    }
}

// =================================================================================
// launch
// =================================================================================
extern "C" void kernel_launch(void* const* d_in, const int* in_sizes, int n_in,
                              void* d_out, int out_size)
{
    const float* x        = (const float*)d_in[0];
    const float* cache_k  = (const float*)d_in[1];
    const float* cache_v  = (const float*)d_in[2];
    const float* Wq       = (const float*)d_in[3];
    const float* bq       = (const float*)d_in[4];
    const float* Wk       = (const float*)d_in[5];
    const float* bk       = (const float*)d_in[6];
    const float* Wv       = (const float*)d_in[7];
    const float* bv       = (const float*)d_in[8];
    const float* Wo       = (const float*)d_in[9];
    const float* bo       = (const float*)d_in[10];
    float*       out      = (float*)d_out;

    static const size_t attn_smem = (size_t)ATTN_SMEM_FLOATS * sizeof(float);
    cudaFuncSetAttribute(attn_kernel, cudaFuncAttributeMaxDynamicSharedMemorySize,
                         (int)attn_smem);

    conv_all<<<2112, 256>>>(Wq, Wk, Wv, Wo, x);

    dim3 gq(4, 96);
    gemm_bf16<0><<<gq, 256>>>(bq, bk, bv);

    attn_kernel<<<NB * NH, 256, attn_smem>>>(cache_k, cache_v);

    dim3 go(4, 32, 4);
    gemm_bf16<1><<<go, 256>>>(nullptr, nullptr, nullptr);

    reduce_bias<<<512, 256>>>(bo, out);
}